// round 7
// baseline (speedup 1.0000x reference)
#include <cuda_runtime.h>

// Problem constants
#define BB 256
#define TT 1024
#define VV 6
#define DD 64
#define UU 64
#define GG 256   // 4*U gate columns

// Precomputed per-vocab tables (V=6).
// Forward table PERMUTED: slot = 4*u + gi, so thread u reads its {i,f,g,o}
// seeds as one conflict-free LDS.128.
__device__ float g_xprojF[VV][GG];
__device__ float g_xprojB[VV][GG];   // unpermuted (epilogue indexes by gate)
__device__ int   g_maskv[VV];
// g/o recurrent weights, k-paired, laid out [kpair j][unit u] = 16B
// {Wr[2j][128+u],Wr[2j+1][128+u], Wr[2j][192+u],Wr[2j+1][192+u]}.
__device__ float4 g_wgo[32][UU];

__device__ __forceinline__ float sigmoid_fast(float x) {
    return __fdividef(1.f, 1.f + __expf(-x));
}
__device__ __forceinline__ float tanh_fast(float x) {
    return 2.f * __fdividef(1.f, 1.f + __expf(-2.f * x)) - 1.f;
}

__device__ __forceinline__ unsigned long long pack2(float lo, float hi) {
    unsigned long long r;
    asm("mov.b64 %0, {%1, %2};" : "=l"(r) : "f"(lo), "f"(hi));
    return r;
}
__device__ __forceinline__ void unpack2(unsigned long long v, float& lo, float& hi) {
    asm("mov.b64 {%0, %1}, %2;" : "=f"(lo), "=f"(hi) : "l"(v));
}
// Packed dual-FMA: lanes {lo,hi} independently (sm_10x FFMA2 path)
#define FMA2(d, a, b, c) \
    asm("fma.rn.f32x2 %0, %1, %2, %3;" : "=l"(d) : "l"(a), "l"(b), "l"(c))
#define ADD2(d, a, b) \
    asm("add.rn.f32x2 %0, %1, %2;" : "=l"(d) : "l"(a), "l"(b))

__global__ void precompute_kernel(const float* __restrict__ emb,
                                  const float* __restrict__ Wk_f,
                                  const float* __restrict__ b_f,
                                  const float* __restrict__ Wk_b,
                                  const float* __restrict__ b_b) {
    int v = blockIdx.x;
    int g = threadIdx.x;          // original gate column
    float sf = 0.f, sb = 0.f;
    #pragma unroll 8
    for (int k = 0; k < DD; k++) {
        float e = emb[v * DD + k];
        sf = fmaf(e, Wk_f[k * GG + g], sf);
        sb = fmaf(e, Wk_b[k * GG + g], sb);
    }
    int u = g & 63, gi = g >> 6;
    g_xprojF[v][4 * u + gi] = sf + b_f[g];
    g_xprojB[v][g]          = sb + b_b[g];
    if (g == 0) {
        int m = 0;
        for (int k = 0; k < DD; k++) m |= (emb[v * DD + k] != 0.f);
        g_maskv[v] = m;
    }
}

// Build the g/o streamed-weight image.
__global__ void prep_wgo_kernel(const float* __restrict__ Wr_f) {
    int idx = blockIdx.x * blockDim.x + threadIdx.x;   // 0..2047
    if (idx >= 32 * UU) return;
    int j = idx / UU, u = idx % UU;
    g_wgo[j][u] = make_float4(Wr_f[(2 * j) * GG + 2 * UU + u],
                              Wr_f[(2 * j + 1) * GG + 2 * UU + u],
                              Wr_f[(2 * j) * GG + 3 * UU + u],
                              Wr_f[(2 * j + 1) * GG + 3 * UU + u]);
}

// Grid 128 CTAs x 128 threads. CTA = 2 batches x 64 threads (2 warps each).
// Warps 0,1 (batch0) -> SMSP 0,1; warps 2,3 (batch1) -> SMSP 2,3: one warp
// per SMSP, batches fully decoupled (separate named barriers, no shared
// issue ports). Thread u owns ALL 4 gate columns of unit u: i,f weights in
// registers (64 pairs), g,o weights streamed from smem as conflict-free
// LDS.128. c,h thread-local; no shuffles in the recurrence.
__global__ void __launch_bounds__(128, 1)
lstm_fwd_kernel(const int* __restrict__ tokens,
                const float* __restrict__ Wr_f,
                const float* __restrict__ Wd,
                const float* __restrict__ bd,
                float* __restrict__ out) {
    __shared__ __align__(16) float4 sh_wgo[32][UU];      // 32 KB
    __shared__ __align__(16) float  sh_xF[VV * GG];      // 6 KB (permuted)
    __shared__ int   sh_tok[2][TT];                      // 8 KB
    __shared__ __align__(16) float sh_h[2][2][UU];       // 1 KB
    __shared__ int   sh_mask[VV];
    __shared__ float sh_red[2][2];

    const int tid  = threadIdx.x;
    const int half = tid >> 6;           // 0 or 1 (batch within CTA)
    const int u    = tid & 63;           // unit owned by this thread
    const int b    = blockIdx.x * 2 + half;
    const int lane = tid & 31;
    const int barid = 1 + half;

    // i,f recurrent weight columns as k-pairs (in registers).
    unsigned long long wI[32], wF[32];
    #pragma unroll
    for (int j = 0; j < 32; j++) {
        wI[j] = pack2(Wr_f[(2 * j) * GG + u],        Wr_f[(2 * j + 1) * GG + u]);
        wF[j] = pack2(Wr_f[(2 * j) * GG + UU + u],   Wr_f[(2 * j + 1) * GG + UU + u]);
    }

    // Stage smem: streamed g/o weights, tables, tokens.
    for (int i = tid; i < 32 * UU; i += 128)
        sh_wgo[i >> 6][i & 63] = g_wgo[i >> 6][i & 63];
    for (int i = tid; i < VV * GG; i += 128) sh_xF[i] = (&g_xprojF[0][0])[i];
    for (int i = u; i < TT; i += 64) sh_tok[half][i] = tokens[b * TT + i];
    if (tid < VV) sh_mask[tid] = g_maskv[tid];
    sh_h[half][0][u] = 0.f; sh_h[half][1][u] = 0.f;
    __syncthreads();

    const int* __restrict__ tokp = sh_tok[half];
    float c = 0.f;       // cell state (thread-local)
    float hprev = 0.f;   // previous h for this unit

#define STEP(HR, HW, S) do {                                                   \
    const int tok = tokp[(S)];                                                 \
    const float4 seed = *(const float4*)&sh_xF[tok * GG + 4 * u];              \
    unsigned long long aI0 = 0ull, aI1 = 0ull, aF0 = 0ull, aF1 = 0ull;         \
    unsigned long long aG0 = 0ull, aG1 = 0ull, aO0 = 0ull, aO1 = 0ull;         \
    const ulonglong2* __restrict__ hp = (const ulonglong2*)(HR);               \
    _Pragma("unroll")                                                          \
    for (int jj = 0; jj < 16; jj++) {                                          \
        ulonglong2 h2  = hp[jj];  /* {h[4jj..4jj+1]},{h[4jj+2..4jj+3]} */      \
        ulonglong2 wg0 = *(const ulonglong2*)&sh_wgo[2 * jj][u];               \
        ulonglong2 wg1 = *(const ulonglong2*)&sh_wgo[2 * jj + 1][u];           \
        FMA2(aI0, h2.x, wI[2 * jj],     aI0);                                  \
        FMA2(aF0, h2.x, wF[2 * jj],     aF0);                                  \
        FMA2(aG0, h2.x, wg0.x,          aG0);                                  \
        FMA2(aO0, h2.x, wg0.y,          aO0);                                  \
        FMA2(aI1, h2.y, wI[2 * jj + 1], aI1);                                  \
        FMA2(aF1, h2.y, wF[2 * jj + 1], aF1);                                  \
        FMA2(aG1, h2.y, wg1.x,          aG1);                                  \
        FMA2(aO1, h2.y, wg1.y,          aO1);                                  \
    }                                                                          \
    ADD2(aI0, aI0, aI1); ADD2(aF0, aF0, aF1);                                  \
    ADD2(aG0, aG0, aG1); ADD2(aO0, aO0, aO1);                                  \
    float lo, hi, zi, zf, zg, zo;                                              \
    unpack2(aI0, lo, hi); zi = lo + hi + seed.x;                               \
    unpack2(aF0, lo, hi); zf = lo + hi + seed.y;                               \
    unpack2(aG0, lo, hi); zg = lo + hi + seed.z;                               \
    unpack2(aO0, lo, hi); zo = lo + hi + seed.w;                               \
    float gi_ = sigmoid_fast(zi);                                              \
    float gf_ = sigmoid_fast(zf);                                              \
    float gg_ = tanh_fast(zg);                                                 \
    float go_ = sigmoid_fast(zo);                                              \
    float cn  = fmaf(gf_, c, gi_ * gg_);                                       \
    float hn  = go_ * tanh_fast(cn);                                           \
    const int m = sh_mask[tok];                                                \
    c     = m ? cn : c;                                                        \
    hprev = m ? hn : hprev;                                                    \
    (HW)[u] = hprev;                                                           \
    asm volatile("bar.sync %0, 64;" :: "r"(barid) : "memory");                 \
} while (0)

    float* __restrict__ h0 = sh_h[half][0];
    float* __restrict__ h1 = sh_h[half][1];
    for (int s = 0; s < TT; s += 2) {
        STEP(h0, h1, s);
        STEP(h1, h0, s + 1);
    }
#undef STEP

    // Final forward h is in buf 0 (step 1023 wrote h0).
    // Backward direction = its first step only (h0=c0=0): z = xprojB(x[T-1]),
    // c = i*g, h_b = o*tanh(c), masked -> 0.
    {
        const int tokL = tokp[TT - 1];
        float ii = sigmoid_fast(g_xprojB[tokL][u]);
        float gg = tanh_fast  (g_xprojB[tokL][2 * UU + u]);
        float oo = sigmoid_fast(g_xprojB[tokL][3 * UU + u]);
        float hb = sh_mask[tokL] ? oo * tanh_fast(ii * gg) : 0.f;

        float contrib = sh_h[half][0][u] * Wd[u] + hb * Wd[UU + u];
        #pragma unroll
        for (int off = 16; off > 0; off >>= 1)
            contrib += __shfl_down_sync(0xffffffffu, contrib, off);
        if (lane == 0) sh_red[half][u >> 5] = contrib;
    }
    asm volatile("bar.sync %0, 64;" :: "r"(barid) : "memory");
    if (u == 0) out[b] = sh_red[half][0] + sh_red[half][1] + bd[0];
}

// Input order (metadata): tokens, emb, Wk_f, Wr_f, b_f, Wk_b, Wr_b, b_b, Wd, bd
extern "C" void kernel_launch(void* const* d_in, const int* in_sizes, int n_in,
                              void* d_out, int out_size) {
    const int*   tokens = (const int*)  d_in[0];
    const float* emb    = (const float*)d_in[1];
    const float* Wk_f   = (const float*)d_in[2];
    const float* Wr_f   = (const float*)d_in[3];
    const float* b_f    = (const float*)d_in[4];
    const float* Wk_b   = (const float*)d_in[5];
    // d_in[6] = Wr_b: unused (backward recurrence collapses to step 1 from h0=0)
    const float* b_b    = (const float*)d_in[7];
    const float* Wd     = (const float*)d_in[8];
    const float* bd     = (const float*)d_in[9];
    float*       out    = (float*)d_out;

    precompute_kernel<<<VV, GG>>>(emb, Wk_f, b_f, Wk_b, b_b);
    prep_wgo_kernel<<<8, 256>>>(Wr_f);
    lstm_fwd_kernel<<<BB / 2, 128>>>(tokens, Wr_f, Wd, bd, out);
}

// round 9
// speedup vs baseline: 1.1367x; 1.1367x over previous
#include <cuda_runtime.h>

// Problem constants
#define BB 256
#define TT 1024
#define VV 6
#define DD 64
#define UU 64
#define GG 256   // 4*U gate columns

// Precomputed per-vocab tables (V=6).
// Forward table PERMUTED for the 128-thread/batch mapping: thread l (u=l>>1,
// p=l&1) owns cols {p*64+u, 128+p*64+u} and reads slots {2l, 2l+1} as LDS.64.
// Original col g (gi=g>>6, u=g&63) -> slot 4u + 2*(gi&1) + (gi>>1).
__device__ float g_xprojF[VV][GG];
__device__ float g_xprojB[VV][GG];   // unpermuted (epilogue indexes by gate)
__device__ int   g_maskv[VV];

__device__ __forceinline__ float sigmoid_fast(float x) {
    return __fdividef(1.f, 1.f + __expf(-x));
}
__device__ __forceinline__ float tanh_fast(float x) {
    return 2.f * __fdividef(1.f, 1.f + __expf(-2.f * x)) - 1.f;
}

__device__ __forceinline__ unsigned long long pack2(float lo, float hi) {
    unsigned long long r;
    asm("mov.b64 %0, {%1, %2};" : "=l"(r) : "f"(lo), "f"(hi));
    return r;
}
__device__ __forceinline__ void unpack2(unsigned long long v, float& lo, float& hi) {
    asm("mov.b64 {%0, %1}, %2;" : "=f"(lo), "=f"(hi) : "l"(v));
}
// Packed dual-FMA: lanes {lo,hi} independently (sm_10x FFMA2 path, rt1)
#define FMA2(d, a, b, c) \
    asm("fma.rn.f32x2 %0, %1, %2, %3;" : "=l"(d) : "l"(a), "l"(b), "l"(c))
#define ADD2(d, a, b) \
    asm("add.rn.f32x2 %0, %1, %2;" : "=l"(d) : "l"(a), "l"(b))

__global__ void precompute_kernel(const float* __restrict__ emb,
                                  const float* __restrict__ Wk_f,
                                  const float* __restrict__ b_f,
                                  const float* __restrict__ Wk_b,
                                  const float* __restrict__ b_b) {
    int v = blockIdx.x;
    int g = threadIdx.x;          // original gate column
    float sf = 0.f, sb = 0.f;
    #pragma unroll 8
    for (int k = 0; k < DD; k++) {
        float e = emb[v * DD + k];
        sf = fmaf(e, Wk_f[k * GG + g], sf);
        sb = fmaf(e, Wk_b[k * GG + g], sb);
    }
    int u = g & 63, gi = g >> 6;
    int slot = 4 * u + 2 * (gi & 1) + (gi >> 1);
    g_xprojF[v][slot] = sf + b_f[g];
    g_xprojB[v][g]    = sb + b_b[g];
    if (g == 0) {
        int m = 0;
        for (int k = 0; k < DD; k++) m |= (emb[v * DD + k] != 0.f);
        g_maskv[v] = m;
    }
}

// Grid 128 CTAs x 256 threads: 1 CTA/SM (uniform single wave), 8 warps/SM =
// 2 warps/SMSP, one from each of the CTA's two INDEPENDENT batch halves.
// Half = 128 threads = one batch. Thread l: u = l>>1, p = l&1;
// A (p=0) owns cols {u (i), 128+u (g)}; B (p=1) owns {64+u (f), 192+u (o)}.
// Matvec: 64 FMA2/thread (k-paired), weights register-resident, h read as
// broadcast LDS.128. A sends sigmoid(i)*tanh(g) to B via one shfl_xor.
// Half 1 is phase-staggered ~400 cyc at entry so the halves anti-phase:
// each half's act/barrier tail hides under the other's FMA burst.
__global__ void __launch_bounds__(256, 1)
lstm_fwd_kernel(const int* __restrict__ tokens,
                const float* __restrict__ Wr_f,
                const float* __restrict__ Wd,
                const float* __restrict__ bd,
                float* __restrict__ out) {
    __shared__ float sh_xF[VV * GG];                 // 6 KB (permuted)
    __shared__ int   sh_tok[2][TT + 1];              // +1: pad for prefetch
    __shared__ __align__(16) float sh_h[2][2][UU];   // [half][buf][unit]
    __shared__ int   sh_mask[VV];
    __shared__ float sh_red[2][2];
    __shared__ float sh_sink;

    const int tid  = threadIdx.x;
    const int half = tid >> 7;           // 0 or 1
    const int l    = tid & 127;          // local id within half
    const int b    = blockIdx.x * 2 + half;
    const int u    = l >> 1;
    const int p    = l & 1;              // 0 = A{i,g}, 1 = B{f,o}
    const int colA = p * UU + u;         // i or f
    const int colB = 2 * UU + p * UU + u;// g or o
    const int lane = tid & 31;
    const int barid = 1 + half;

    // Recurrent weight columns as k-pairs (register-resident).
    unsigned long long wA[32], wB[32];
    #pragma unroll
    for (int j = 0; j < 32; j++) {
        wA[j] = pack2(Wr_f[(2 * j) * GG + colA], Wr_f[(2 * j + 1) * GG + colA]);
        wB[j] = pack2(Wr_f[(2 * j) * GG + colB], Wr_f[(2 * j + 1) * GG + colB]);
    }

    // Stage tokens (per half) and tables (whole CTA).
    for (int i = l; i < TT; i += 128) sh_tok[half][i] = tokens[b * TT + i];
    if (l == 0) sh_tok[half][TT] = 0;    // prefetch pad
    for (int i = tid; i < VV * GG; i += 256) sh_xF[i] = (&g_xprojF[0][0])[i];
    if (tid < VV) sh_mask[tid] = g_maskv[tid];
    if (l < UU) { sh_h[half][0][l] = 0.f; sh_h[half][1][l] = 0.f; }
    __syncthreads();

    // Anti-phase stagger: half 1 burns ~400 cyc in a dependent FFMA chain.
    // (Offset persists: under shared-pipe contention the finish-time
    // separation between the halves is step-invariant.)
    if (half == 1) {
        float d = (float)(l + 1) * 1e-30f;
        #pragma unroll
        for (int i = 0; i < 100; i++) d = fmaf(d, 1.0000001f, 1e-30f);
        if (d == 1.2345e30f && l == 1) sh_sink = d;   // never true; defeats DCE
    }

    const int* __restrict__ tokp = sh_tok[half];
    float c = 0.f;       // cell state (live in B threads)
    float hprev = 0.f;   // previous h for this unit (live in B threads)

    // First-step prefetch: token 0's seed and mask.
    int    tok  = tokp[0];
    float2 seed = *(const float2*)&sh_xF[tok * GG + 2 * l];
    int    m    = sh_mask[tok];

#define STEP(HR, HW, S) do {                                                   \
    /* accumulate z; seed folded into acc0 lanes */                            \
    unsigned long long aA0 = pack2(seed.x, 0.f);                               \
    unsigned long long aB0 = pack2(seed.y, 0.f);                               \
    unsigned long long aA1 = 0ull, aA2 = 0ull, aA3 = 0ull;                     \
    unsigned long long aB1 = 0ull, aB2 = 0ull, aB3 = 0ull;                     \
    const ulonglong2* __restrict__ hp = (const ulonglong2*)(HR);               \
    _Pragma("unroll")                                                          \
    for (int i = 0; i < 16; i += 2) {                                          \
        ulonglong2 pX = hp[i];       /* {h4i,h4i+1},{h4i+2,h4i+3} */           \
        ulonglong2 pY = hp[i + 1];                                             \
        FMA2(aA0, pX.x, wA[2 * i + 0], aA0);                                   \
        FMA2(aB0, pX.x, wB[2 * i + 0], aB0);                                   \
        FMA2(aA1, pX.y, wA[2 * i + 1], aA1);                                   \
        FMA2(aB1, pX.y, wB[2 * i + 1], aB1);                                   \
        FMA2(aA2, pY.x, wA[2 * i + 2], aA2);                                   \
        FMA2(aB2, pY.x, wB[2 * i + 2], aB2);                                   \
        FMA2(aA3, pY.y, wA[2 * i + 3], aA3);                                   \
        FMA2(aB3, pY.y, wB[2 * i + 3], aB3);                                   \
    }                                                                          \
    ADD2(aA0, aA0, aA1); ADD2(aA2, aA2, aA3); ADD2(aA0, aA0, aA2);             \
    ADD2(aB0, aB0, aB1); ADD2(aB2, aB2, aB3); ADD2(aB0, aB0, aB2);             \
    float zAl, zAh, zBl, zBh;                                                  \
    unpack2(aA0, zAl, zAh); unpack2(aB0, zBl, zBh);                            \
    float zA = zAl + zAh;            /* i or f */                              \
    float zB = zBl + zBh;            /* g or o */                              \
    float actA = sigmoid_fast(zA);                                             \
    float actB = (p == 0) ? tanh_fast(zB) : sigmoid_fast(zB);                  \
    float sendv = actA * actB;       /* A: i*g ; B: unused */                  \
    float ig = __shfl_xor_sync(0xffffffffu, sendv, 1);                         \
    if (p == 1) {                                                              \
        float cn = fmaf(actA, c, ig);        /* f*c + i*g */                   \
        float hn = actB * tanh_fast(cn);     /* o * tanh(c) */                 \
        c     = m ? cn : c;                                                    \
        hprev = m ? hn : hprev;                                                \
        (HW)[u] = hprev;                                                       \
    }                                                                          \
    /* prefetch next step's token/seed/mask BEFORE the barrier (tables are */  \
    /* init-constant, so this is barrier-independent) */                       \
    tok  = tokp[(S) + 1];                                                      \
    seed = *(const float2*)&sh_xF[tok * GG + 2 * l];                           \
    m    = sh_mask[tok];                                                       \
    asm volatile("bar.sync %0, 128;" :: "r"(barid) : "memory");                \
} while (0)

    float* __restrict__ h0 = sh_h[half][0];
    float* __restrict__ h1 = sh_h[half][1];
    for (int s = 0; s < TT; s += 2) {
        STEP(h0, h1, s);
        STEP(h1, h0, s + 1);
    }
#undef STEP

    // Final forward h is in buf 0 (step 1023 wrote h0).
    // Backward direction = its first step only (h0=c0=0): z = xprojB(x[T-1]),
    // c = i*g, h_b = o*tanh(c), masked -> 0.
    if (l < UU) {
        const int tokL = tokp[TT - 1];
        float ii = sigmoid_fast(g_xprojB[tokL][l]);
        float gg = tanh_fast  (g_xprojB[tokL][2 * UU + l]);
        float oo = sigmoid_fast(g_xprojB[tokL][3 * UU + l]);
        float hb = sh_mask[tokL] ? oo * tanh_fast(ii * gg) : 0.f;

        float contrib = sh_h[half][0][l] * Wd[l] + hb * Wd[UU + l];
        #pragma unroll
        for (int off = 16; off > 0; off >>= 1)
            contrib += __shfl_down_sync(0xffffffffu, contrib, off);
        if (lane == 0) sh_red[half][l >> 5] = contrib;
    }
    asm volatile("bar.sync %0, 128;" :: "r"(barid) : "memory");
    if (l == 0) out[b] = sh_red[half][0] + sh_red[half][1] + bd[0];
}

// Input order (metadata): tokens, emb, Wk_f, Wr_f, b_f, Wk_b, Wr_b, b_b, Wd, bd
extern "C" void kernel_launch(void* const* d_in, const int* in_sizes, int n_in,
                              void* d_out, int out_size) {
    const int*   tokens = (const int*)  d_in[0];
    const float* emb    = (const float*)d_in[1];
    const float* Wk_f   = (const float*)d_in[2];
    const float* Wr_f   = (const float*)d_in[3];
    const float* b_f    = (const float*)d_in[4];
    const float* Wk_b   = (const float*)d_in[5];
    // d_in[6] = Wr_b: unused (backward recurrence collapses to step 1 from h0=0)
    const float* b_b    = (const float*)d_in[7];
    const float* Wd     = (const float*)d_in[8];
    const float* bd     = (const float*)d_in[9];
    float*       out    = (float*)d_out;

    precompute_kernel<<<VV, GG>>>(emb, Wk_f, b_f, Wk_b, b_b);
    lstm_fwd_kernel<<<BB / 2, 256>>>(tokens, Wr_f, Wd, bd, out);
}